// round 15
// baseline (speedup 1.0000x reference)
#include <cuda_runtime.h>
#include <cstdint>

#define NPIX  9216
#define CCH   72
#define BATCH 2
#define BM    128
#define BN    64
#define NT    (NPIX / BN)     // 144 key tiles
#define QTILES (NPIX / BM)    // 72 query tiles per batch

// Device scratch (allocation-free rule: __device__ globals).
__device__ __align__(16) float g_Q[BATCH * CCH * NPIX];   // [b][c][n]
__device__ __align__(16) float g_K[BATCH * CCH * NPIX];   // [b][c][n]
__device__ __align__(16) float g_V[BATCH * NPIX * CCH];   // [b][n][c]

typedef unsigned long long u64;

union F4U2 { float4 f; u64 u[2]; };

__device__ __forceinline__ u64 pack2(float x, float y) {
    u64 r; asm("mov.b64 %0, {%1, %2};" : "=l"(r) : "f"(x), "f"(y)); return r;
}
__device__ __forceinline__ void unpack2(u64 v, float& x, float& y) {
    asm("mov.b64 {%0, %1}, %2;" : "=f"(x), "=f"(y) : "l"(v));
}
__device__ __forceinline__ void fma2(u64& d, u64 a, u64 b) {
    asm("fma.rn.f32x2 %0, %1, %2, %0;" : "+l"(d) : "l"(a), "l"(b));
}
__device__ __forceinline__ u64 mul2(u64 a, u64 b) {
    u64 d; asm("mul.rn.f32x2 %0, %1, %2;" : "=l"(d) : "l"(a), "l"(b)); return d;
}
__device__ __forceinline__ void cp_async16(uint32_t dst, const void* src) {
    asm volatile("cp.async.cg.shared.global [%0], [%1], 16;" :: "r"(dst), "l"(src));
}
__device__ __forceinline__ void cp_commit() { asm volatile("cp.async.commit_group;"); }
__device__ __forceinline__ void cp_wait1()  { asm volatile("cp.async.wait_group 1;"); }

// ---------------------------------------------------------------------------
// Kernel 1: QKV projection.  q[d,n] = sum_c W[d,c] x[c,n] + b[d]
// Q,K stored channel-major [b][c][n]; V stored pixel-major [b][n][c].
// ---------------------------------------------------------------------------
__global__ void __launch_bounds__(256, 1)
qkv_kernel(const float* __restrict__ x,
           const float* __restrict__ Wq, const float* __restrict__ bq,
           const float* __restrict__ Wk, const float* __restrict__ bk,
           const float* __restrict__ Wv, const float* __restrict__ bv) {
    extern __shared__ float sm[];
    float* xs  = sm;                 // [72][128]
    float* ws  = xs + CCH * BM;      // [72][72]
    float* vst = ws + CCH * CCH;     // [128][72] staging for coalesced V store

    const int tid = threadIdx.x;
    const int b  = blockIdx.y;
    const int n0 = blockIdx.x * BM;

    // load x tile (channel-major), coalesced float4
    {
        float4* xs4 = reinterpret_cast<float4*>(xs);
        for (int i = tid; i < CCH * (BM / 4); i += 256) {
            int c = i >> 5, m4 = i & 31;
            xs4[c * 32 + m4] =
                *reinterpret_cast<const float4*>(x + (size_t)(b * CCH + c) * NPIX + n0 + m4 * 4);
        }
    }

    const float* Ws[3] = {Wq, Wk, Wv};
    const float* bs[3] = {bq, bk, bv};

    const int td = tid >> 5;        // 0..7  -> 9 output channels each
    const int tn = tid & 31;        // 0..31 -> 4 pixels each
    const int d0 = td * 9;

    for (int mat = 0; mat < 3; ++mat) {
        __syncthreads();
        {
            const float* W = Ws[mat];
            for (int i = tid; i < CCH * CCH; i += 256) ws[i] = W[i];
        }
        __syncthreads();

        float acc[9][4];
#pragma unroll
        for (int k = 0; k < 9; ++k) {
            float bb = __ldg(bs[mat] + d0 + k);
            acc[k][0] = bb; acc[k][1] = bb; acc[k][2] = bb; acc[k][3] = bb;
        }
        const float4* xs4 = reinterpret_cast<const float4*>(xs);
#pragma unroll 4
        for (int c = 0; c < CCH; ++c) {
            float4 xv = xs4[c * 32 + tn];
#pragma unroll
            for (int k = 0; k < 9; ++k) {
                float w = ws[(d0 + k) * CCH + c];
                acc[k][0] = fmaf(w, xv.x, acc[k][0]);
                acc[k][1] = fmaf(w, xv.y, acc[k][1]);
                acc[k][2] = fmaf(w, xv.z, acc[k][2]);
                acc[k][3] = fmaf(w, xv.w, acc[k][3]);
            }
        }

        if (mat < 2) {
            float* g = (mat == 0) ? g_Q : g_K;
#pragma unroll
            for (int k = 0; k < 9; ++k) {
                float4 v4 = make_float4(acc[k][0], acc[k][1], acc[k][2], acc[k][3]);
                *reinterpret_cast<float4*>(g + (size_t)(b * CCH + d0 + k) * NPIX + n0 + tn * 4) = v4;
            }
        } else {
#pragma unroll
            for (int k = 0; k < 9; ++k)
#pragma unroll
                for (int jj = 0; jj < 4; ++jj)
                    vst[(tn * 4 + jj) * CCH + d0 + k] = acc[k][jj];
            __syncthreads();
            float4* vg = reinterpret_cast<float4*>(g_V + (size_t)(b * NPIX + n0) * CCH);
            const float4* vs4 = reinterpret_cast<const float4*>(vst);
            for (int i = tid; i < BM * CCH / 4; i += 256) vg[i] = vs4[i];
        }
    }
}

// ---------------------------------------------------------------------------
// Kernel 2: flash attention + fused grouped pooling epilogue.
// One CTA = 128 queries, 256 threads as (tm 0..15) x (tn 0..15).
// QK: per-thread 8M x 4N (m-paired FFMA2). PV: per-thread 8M x 5C (Cpad=80).
// Row stats replicated across the 16 tn lanes -> no stats smem, 3 barriers/tile.
// ---------------------------------------------------------------------------
__global__ void __launch_bounds__(256, 1)
attn_kernel(const float* __restrict__ x, float* __restrict__ out) {
    extern __shared__ float sm[];
    float* Qs = sm;                         // [72][128]   (reused for wv^T at end)
    float* Ks = Qs + CCH * BM;              // [2][72][64]
    float* Vs = Ks + 2 * CCH * BN;          // [2][64][80] (cols 72..79 zero pad)
    float* Pt = Vs + 2 * BN * 80;           // [64][132]   (P transposed, +4 pad)

    const int tid = threadIdx.x;
    const int tm = tid >> 4;                // 0..15 -> rows tm*8 .. tm*8+7
    const int tn = tid & 15;                // 0..15
    const int b  = blockIdx.y;
    const int n0 = blockIdx.x * BM;

    // zero Vs pad columns once (accumulators for c>=72 are discarded but must be finite)
    for (int i = tid; i < 2 * BN * 8; i += 256) {
        int bu = i >> 9, row = (i >> 3) & 63, cc = i & 7;
        Vs[bu * BN * 80 + row * 80 + 72 + cc] = 0.0f;
    }

    // load Q tile channel-major: Qs[c][m]
    {
        float4* Qs4 = reinterpret_cast<float4*>(Qs);
        for (int i = tid; i < CCH * (BM / 4); i += 256) {
            int c = i >> 5, m4 = i & 31;
            Qs4[c * 32 + m4] =
                *reinterpret_cast<const float4*>(g_Q + (size_t)(b * CCH + c) * NPIX + n0 + m4 * 4);
        }
    }

    const uint32_t ks_u = (uint32_t)__cvta_generic_to_shared(Ks);
    const uint32_t vs_u = (uint32_t)__cvta_generic_to_shared(Vs);

    auto prefetch = [&](int kt, int bu) {
        // K tile: [72][64] floats, source channel-major
        const float* kg = g_K + (size_t)(b * CCH) * NPIX + kt * BN;
        for (int i = tid; i < 1152; i += 256) {           // 1152 float4
            int c = i >> 4, j4 = i & 15;
            cp_async16(ks_u + (uint32_t)((bu * CCH * BN + c * BN + j4 * 4) * 4),
                       kg + (size_t)c * NPIX + j4 * 4);
        }
        // V tile: [64][72] floats (stride 80 in smem), source pixel-major
        const float* vg = g_V + (size_t)(b * NPIX + kt * BN) * CCH;
        for (int i = tid; i < 1152; i += 256) {
            int row = i / 18, c4 = i % 18;
            cp_async16(vs_u + (uint32_t)((bu * BN * 80 + row * 80 + c4 * 4) * 4),
                       vg + (size_t)row * CCH + c4 * 4);
        }
    };

    prefetch(0, 0);
    cp_commit();

    u64 o2[4][5];                            // PV accumulators (m-paired)
#pragma unroll
    for (int mp = 0; mp < 4; ++mp)
#pragma unroll
        for (int cp = 0; cp < 5; ++cp) o2[mp][cp] = 0ull;
    float mrow[8], lrow[8];
#pragma unroll
    for (int r = 0; r < 8; ++r) { mrow[r] = -1e30f; lrow[r] = 0.0f; }

    for (int kt = 0; kt < NT; ++kt) {
        const int bu = kt & 1;
        if (kt + 1 < NT) prefetch(kt + 1, bu ^ 1);
        cp_commit();                          // always commit (keeps group count)
        cp_wait1();
        __syncthreads();                      // (1) buf[kt&1] ready everywhere

        // ---------------- QK: S[128x64], K-dim = 72 ----------------
        u64 s2[4][4];
#pragma unroll
        for (int mp = 0; mp < 4; ++mp)
#pragma unroll
            for (int cc = 0; cc < 4; ++cc) s2[mp][cc] = 0ull;

        const float4* qp = reinterpret_cast<const float4*>(Qs) + tm * 2;
        const float4* kp = reinterpret_cast<const float4*>(Ks + bu * CCH * BN) + tn;
#pragma unroll 8
        for (int c = 0; c < CCH; ++c) {
            F4U2 a0, a1;
            a0.f = qp[c * 32];
            a1.f = qp[c * 32 + 1];
            float4 bb = kp[c * 16];
            u64 ap[4] = {a0.u[0], a0.u[1], a1.u[0], a1.u[1]};
            u64 br[4];
            br[0] = pack2(bb.x, bb.x); br[1] = pack2(bb.y, bb.y);
            br[2] = pack2(bb.z, bb.z); br[3] = pack2(bb.w, bb.w);
#pragma unroll
            for (int mp = 0; mp < 4; ++mp)
#pragma unroll
                for (int cc = 0; cc < 4; ++cc)
                    fma2(s2[mp][cc], ap[mp], br[cc]);
        }

        // ---------------- online softmax (row stats replicated over tn) -----
        float sv[8][4];
#pragma unroll
        for (int mp = 0; mp < 4; ++mp)
#pragma unroll
            for (int cc = 0; cc < 4; ++cc)
                unpack2(s2[mp][cc], sv[2 * mp][cc], sv[2 * mp + 1][cc]);

        float scl[8];
#pragma unroll
        for (int r = 0; r < 8; ++r) {
            float tmax = fmaxf(fmaxf(sv[r][0], sv[r][1]), fmaxf(sv[r][2], sv[r][3]));
#pragma unroll
            for (int w = 1; w < 16; w <<= 1)
                tmax = fmaxf(tmax, __shfl_xor_sync(0xffffffffu, tmax, w));
            float mnew = fmaxf(mrow[r], tmax);
            scl[r] = __expf(mrow[r] - mnew);
            float ps = 0.f;
#pragma unroll
            for (int cc = 0; cc < 4; ++cc) {
                float p = __expf(sv[r][cc] - mnew);
                sv[r][cc] = p;
                ps += p;
            }
#pragma unroll
            for (int w = 1; w < 16; w <<= 1)
                ps += __shfl_xor_sync(0xffffffffu, ps, w);
            lrow[r] = lrow[r] * scl[r] + ps;
            mrow[r] = mnew;
        }

        // write P transposed: Pt[j][m], stride 132
#pragma unroll
        for (int cc = 0; cc < 4; ++cc) {
            int j = tn * 4 + cc;
            float4* dst = reinterpret_cast<float4*>(Pt + j * 132 + tm * 8);
            dst[0] = make_float4(sv[0][cc], sv[1][cc], sv[2][cc], sv[3][cc]);
            dst[1] = make_float4(sv[4][cc], sv[5][cc], sv[6][cc], sv[7][cc]);
        }
        __syncthreads();                      // (2) Pt ready

        // ---------------- PV: O[128x72] += P[128x64] V[64x72] ---------------
        u64 sc2[4];
#pragma unroll
        for (int mp = 0; mp < 4; ++mp) sc2[mp] = pack2(scl[2 * mp], scl[2 * mp + 1]);
#pragma unroll
        for (int mp = 0; mp < 4; ++mp)
#pragma unroll
            for (int cp = 0; cp < 5; ++cp)
                o2[mp][cp] = mul2(o2[mp][cp], sc2[mp]);

        const float4* pp = reinterpret_cast<const float4*>(Pt) + tm * 2;
        const float* vp = Vs + bu * BN * 80 + tn * 5;
#pragma unroll 4
        for (int j = 0; j < BN; ++j) {
            F4U2 p0, p1;
            p0.f = pp[j * 33];
            p1.f = pp[j * 33 + 1];
            u64 pr[4] = {p0.u[0], p0.u[1], p1.u[0], p1.u[1]};
            u64 vr[5];
#pragma unroll
            for (int cp = 0; cp < 5; ++cp) {
                float v = vp[j * 80 + cp];
                vr[cp] = pack2(v, v);
            }
#pragma unroll
            for (int mp = 0; mp < 4; ++mp)
#pragma unroll
                for (int cp = 0; cp < 5; ++cp)
                    fma2(o2[mp][cp], pr[mp], vr[cp]);
        }
        __syncthreads();                      // (3) done reading buf & Pt
    }

    // ---------------- epilogue: normalize, then fused grouped pooling -------
    // write wv^T into Qs (Q no longer needed): Qs[c][m] = O[m][c] / l[m]
#pragma unroll
    for (int mp = 0; mp < 4; ++mp) {
        float inv0 = 1.0f / lrow[2 * mp];
        float inv1 = 1.0f / lrow[2 * mp + 1];
        int m = tm * 8 + 2 * mp;
#pragma unroll
        for (int cp = 0; cp < 5; ++cp) {
            int c = tn * 5 + cp;
            if (c < CCH) {
                float v0, v1;
                unpack2(o2[mp][cp], v0, v1);
                Qs[c * BM + m]     = v0 * inv0;
                Qs[c * BM + m + 1] = v1 * inv1;
            }
        }
    }
    __syncthreads();

    // pooled[b][g][n] = sum_{f<4} x[b][4g+f][n] * wv[b][4g+f][n]
    for (int o = tid; o < 18 * BM; o += 256) {
        int m = o & (BM - 1);
        int g = o >> 7;
        float acc = 0.f;
#pragma unroll
        for (int f = 0; f < 4; ++f) {
            int c = 4 * g + f;
            acc = fmaf(x[(size_t)(b * CCH + c) * NPIX + n0 + m], Qs[c * BM + m], acc);
        }
        out[(size_t)(b * 18 + g) * NPIX + n0 + m] = acc;
    }
}

// ---------------------------------------------------------------------------
extern "C" void kernel_launch(void* const* d_in, const int* in_sizes, int n_in,
                              void* d_out, int out_size) {
    const float* x  = (const float*)d_in[0];
    const float* Wq = (const float*)d_in[1];
    const float* bq = (const float*)d_in[2];
    const float* Wk = (const float*)d_in[3];
    const float* bk = (const float*)d_in[4];
    const float* Wv = (const float*)d_in[5];
    const float* bv = (const float*)d_in[6];

    const int smP = (CCH * BM + CCH * CCH + BM * CCH) * 4;               // 94,464 B
    const int smF = (CCH * BM + 2 * CCH * BN + 2 * BN * 80 + BN * 132) * 4; // 148,480 B
    cudaFuncSetAttribute(qkv_kernel,  cudaFuncAttributeMaxDynamicSharedMemorySize, smP);
    cudaFuncSetAttribute(attn_kernel, cudaFuncAttributeMaxDynamicSharedMemorySize, smF);

    qkv_kernel<<<dim3(QTILES, BATCH), 256, smP>>>(x, Wq, bq, Wk, bk, Wv, bv);
    attn_kernel<<<dim3(QTILES, BATCH), 256, smF>>>(x, (float*)d_out);
}

// round 16
// speedup vs baseline: 1.0004x; 1.0004x over previous
#include <cuda_runtime.h>
#include <cstdint>

#define NPIX  9216
#define CCH   72
#define BATCH 2
#define BM    128
#define BN    64
#define NT    (NPIX / BN)     // 144 key tiles
#define QTILES (NPIX / BM)    // 72 query tiles per batch

// Device scratch (allocation-free rule: __device__ globals).
__device__ __align__(16) float g_Q[BATCH * CCH * NPIX];   // [b][c][n]
__device__ __align__(16) float g_K[BATCH * CCH * NPIX];   // [b][c][n]
__device__ __align__(16) float g_V[BATCH * NPIX * CCH];   // [b][n][c]

typedef unsigned long long u64;

union F4U2 { float4 f; u64 u[2]; };

__device__ __forceinline__ u64 pack2(float x, float y) {
    u64 r; asm("mov.b64 %0, {%1, %2};" : "=l"(r) : "f"(x), "f"(y)); return r;
}
__device__ __forceinline__ void unpack2(u64 v, float& x, float& y) {
    asm("mov.b64 {%0, %1}, %2;" : "=f"(x), "=f"(y) : "l"(v));
}
__device__ __forceinline__ void fma2(u64& d, u64 a, u64 b) {
    asm("fma.rn.f32x2 %0, %1, %2, %0;" : "+l"(d) : "l"(a), "l"(b));
}
__device__ __forceinline__ u64 mul2(u64 a, u64 b) {
    u64 d; asm("mul.rn.f32x2 %0, %1, %2;" : "=l"(d) : "l"(a), "l"(b)); return d;
}
__device__ __forceinline__ void cp_async16(uint32_t dst, const void* src) {
    asm volatile("cp.async.cg.shared.global [%0], [%1], 16;" :: "r"(dst), "l"(src));
}
__device__ __forceinline__ void cp_commit() { asm volatile("cp.async.commit_group;"); }
__device__ __forceinline__ void cp_wait1()  { asm volatile("cp.async.wait_group 1;"); }

// ---------------------------------------------------------------------------
// Kernel 1: QKV projection.  q[d,n] = sum_c W[d,c] x[c,n] + b[d]
// Q,K stored channel-major [b][c][n]; V stored pixel-major [b][n][c].
// ---------------------------------------------------------------------------
__global__ void __launch_bounds__(256, 1)
qkv_kernel(const float* __restrict__ x,
           const float* __restrict__ Wq, const float* __restrict__ bq,
           const float* __restrict__ Wk, const float* __restrict__ bk,
           const float* __restrict__ Wv, const float* __restrict__ bv) {
    extern __shared__ float sm[];
    float* xs  = sm;                 // [72][128]
    float* ws  = xs + CCH * BM;      // [72][72]
    float* vst = ws + CCH * CCH;     // [128][72] staging for coalesced V store

    const int tid = threadIdx.x;
    const int b  = blockIdx.y;
    const int n0 = blockIdx.x * BM;

    // load x tile (channel-major), coalesced float4
    {
        float4* xs4 = reinterpret_cast<float4*>(xs);
        for (int i = tid; i < CCH * (BM / 4); i += 256) {
            int c = i >> 5, m4 = i & 31;
            xs4[c * 32 + m4] =
                *reinterpret_cast<const float4*>(x + (size_t)(b * CCH + c) * NPIX + n0 + m4 * 4);
        }
    }

    const float* Ws[3] = {Wq, Wk, Wv};
    const float* bs[3] = {bq, bk, bv};

    const int td = tid >> 5;        // 0..7  -> 9 output channels each
    const int tn = tid & 31;        // 0..31 -> 4 pixels each
    const int d0 = td * 9;

    for (int mat = 0; mat < 3; ++mat) {
        __syncthreads();
        {
            const float* W = Ws[mat];
            for (int i = tid; i < CCH * CCH; i += 256) ws[i] = W[i];
        }
        __syncthreads();

        float acc[9][4];
#pragma unroll
        for (int k = 0; k < 9; ++k) {
            float bb = __ldg(bs[mat] + d0 + k);
            acc[k][0] = bb; acc[k][1] = bb; acc[k][2] = bb; acc[k][3] = bb;
        }
        const float4* xs4 = reinterpret_cast<const float4*>(xs);
#pragma unroll 4
        for (int c = 0; c < CCH; ++c) {
            float4 xv = xs4[c * 32 + tn];
#pragma unroll
            for (int k = 0; k < 9; ++k) {
                float w = ws[(d0 + k) * CCH + c];
                acc[k][0] = fmaf(w, xv.x, acc[k][0]);
                acc[k][1] = fmaf(w, xv.y, acc[k][1]);
                acc[k][2] = fmaf(w, xv.z, acc[k][2]);
                acc[k][3] = fmaf(w, xv.w, acc[k][3]);
            }
        }

        if (mat < 2) {
            float* g = (mat == 0) ? g_Q : g_K;
#pragma unroll
            for (int k = 0; k < 9; ++k) {
                float4 v4 = make_float4(acc[k][0], acc[k][1], acc[k][2], acc[k][3]);
                *reinterpret_cast<float4*>(g + (size_t)(b * CCH + d0 + k) * NPIX + n0 + tn * 4) = v4;
            }
        } else {
#pragma unroll
            for (int k = 0; k < 9; ++k)
#pragma unroll
                for (int jj = 0; jj < 4; ++jj)
                    vst[(tn * 4 + jj) * CCH + d0 + k] = acc[k][jj];
            __syncthreads();
            float4* vg = reinterpret_cast<float4*>(g_V + (size_t)(b * NPIX + n0) * CCH);
            const float4* vs4 = reinterpret_cast<const float4*>(vst);
            for (int i = tid; i < BM * CCH / 4; i += 256) vg[i] = vs4[i];
        }
    }
}

// ---------------------------------------------------------------------------
// Kernel 2: flash attention + fused grouped pooling epilogue.
// One CTA = 128 queries, 256 threads as (tm 0..15) x (tn 0..15).
// QK: per-thread 8M x 4N (m-paired FFMA2). PV: per-thread 8M x 5C (Cpad=80).
// Row stats replicated across the 16 tn lanes -> no stats smem, 3 barriers/tile.
// ---------------------------------------------------------------------------
__global__ void __launch_bounds__(256, 1)
attn_kernel(const float* __restrict__ x, float* __restrict__ out) {
    extern __shared__ float sm[];
    float* Qs = sm;                         // [72][128]   (reused for wv^T at end)
    float* Ks = Qs + CCH * BM;              // [2][72][64]
    float* Vs = Ks + 2 * CCH * BN;          // [2][64][80] (cols 72..79 zero pad)
    float* Pt = Vs + 2 * BN * 80;           // [64][132]   (P transposed, +4 pad)

    const int tid = threadIdx.x;
    const int tm = tid >> 4;                // 0..15 -> rows tm*8 .. tm*8+7
    const int tn = tid & 15;                // 0..15
    const int b  = blockIdx.y;
    const int n0 = blockIdx.x * BM;

    // zero Vs pad columns once (accumulators for c>=72 are discarded but must be finite)
    for (int i = tid; i < 2 * BN * 8; i += 256) {
        int bu = i >> 9, row = (i >> 3) & 63, cc = i & 7;
        Vs[bu * BN * 80 + row * 80 + 72 + cc] = 0.0f;
    }

    // load Q tile channel-major: Qs[c][m]
    {
        float4* Qs4 = reinterpret_cast<float4*>(Qs);
        for (int i = tid; i < CCH * (BM / 4); i += 256) {
            int c = i >> 5, m4 = i & 31;
            Qs4[c * 32 + m4] =
                *reinterpret_cast<const float4*>(g_Q + (size_t)(b * CCH + c) * NPIX + n0 + m4 * 4);
        }
    }

    const uint32_t ks_u = (uint32_t)__cvta_generic_to_shared(Ks);
    const uint32_t vs_u = (uint32_t)__cvta_generic_to_shared(Vs);

    auto prefetch = [&](int kt, int bu) {
        // K tile: [72][64] floats, source channel-major
        const float* kg = g_K + (size_t)(b * CCH) * NPIX + kt * BN;
        for (int i = tid; i < 1152; i += 256) {           // 1152 float4
            int c = i >> 4, j4 = i & 15;
            cp_async16(ks_u + (uint32_t)((bu * CCH * BN + c * BN + j4 * 4) * 4),
                       kg + (size_t)c * NPIX + j4 * 4);
        }
        // V tile: [64][72] floats (stride 80 in smem), source pixel-major
        const float* vg = g_V + (size_t)(b * NPIX + kt * BN) * CCH;
        for (int i = tid; i < 1152; i += 256) {
            int row = i / 18, c4 = i % 18;
            cp_async16(vs_u + (uint32_t)((bu * BN * 80 + row * 80 + c4 * 4) * 4),
                       vg + (size_t)row * CCH + c4 * 4);
        }
    };

    prefetch(0, 0);
    cp_commit();

    u64 o2[4][5];                            // PV accumulators (m-paired)
#pragma unroll
    for (int mp = 0; mp < 4; ++mp)
#pragma unroll
        for (int cp = 0; cp < 5; ++cp) o2[mp][cp] = 0ull;
    float mrow[8], lrow[8];
#pragma unroll
    for (int r = 0; r < 8; ++r) { mrow[r] = -1e30f; lrow[r] = 0.0f; }

    for (int kt = 0; kt < NT; ++kt) {
        const int bu = kt & 1;
        if (kt + 1 < NT) prefetch(kt + 1, bu ^ 1);
        cp_commit();                          // always commit (keeps group count)
        cp_wait1();
        __syncthreads();                      // (1) buf[kt&1] ready everywhere

        // ---------------- QK: S[128x64], K-dim = 72 ----------------
        u64 s2[4][4];
#pragma unroll
        for (int mp = 0; mp < 4; ++mp)
#pragma unroll
            for (int cc = 0; cc < 4; ++cc) s2[mp][cc] = 0ull;

        const float4* qp = reinterpret_cast<const float4*>(Qs) + tm * 2;
        const float4* kp = reinterpret_cast<const float4*>(Ks + bu * CCH * BN) + tn;
#pragma unroll 8
        for (int c = 0; c < CCH; ++c) {
            F4U2 a0, a1;
            a0.f = qp[c * 32];
            a1.f = qp[c * 32 + 1];
            float4 bb = kp[c * 16];
            u64 ap[4] = {a0.u[0], a0.u[1], a1.u[0], a1.u[1]};
            u64 br[4];
            br[0] = pack2(bb.x, bb.x); br[1] = pack2(bb.y, bb.y);
            br[2] = pack2(bb.z, bb.z); br[3] = pack2(bb.w, bb.w);
#pragma unroll
            for (int mp = 0; mp < 4; ++mp)
#pragma unroll
                for (int cc = 0; cc < 4; ++cc)
                    fma2(s2[mp][cc], ap[mp], br[cc]);
        }

        // ---------------- online softmax (row stats replicated over tn) -----
        float sv[8][4];
#pragma unroll
        for (int mp = 0; mp < 4; ++mp)
#pragma unroll
            for (int cc = 0; cc < 4; ++cc)
                unpack2(s2[mp][cc], sv[2 * mp][cc], sv[2 * mp + 1][cc]);

        float scl[8];
#pragma unroll
        for (int r = 0; r < 8; ++r) {
            float tmax = fmaxf(fmaxf(sv[r][0], sv[r][1]), fmaxf(sv[r][2], sv[r][3]));
#pragma unroll
            for (int w = 1; w < 16; w <<= 1)
                tmax = fmaxf(tmax, __shfl_xor_sync(0xffffffffu, tmax, w));
            float mnew = fmaxf(mrow[r], tmax);
            scl[r] = __expf(mrow[r] - mnew);
            float ps = 0.f;
#pragma unroll
            for (int cc = 0; cc < 4; ++cc) {
                float p = __expf(sv[r][cc] - mnew);
                sv[r][cc] = p;
                ps += p;
            }
#pragma unroll
            for (int w = 1; w < 16; w <<= 1)
                ps += __shfl_xor_sync(0xffffffffu, ps, w);
            lrow[r] = lrow[r] * scl[r] + ps;
            mrow[r] = mnew;
        }

        // write P transposed: Pt[j][m], stride 132
#pragma unroll
        for (int cc = 0; cc < 4; ++cc) {
            int j = tn * 4 + cc;
            float4* dst = reinterpret_cast<float4*>(Pt + j * 132 + tm * 8);
            dst[0] = make_float4(sv[0][cc], sv[1][cc], sv[2][cc], sv[3][cc]);
            dst[1] = make_float4(sv[4][cc], sv[5][cc], sv[6][cc], sv[7][cc]);
        }
        __syncthreads();                      // (2) Pt ready

        // ---------------- PV: O[128x72] += P[128x64] V[64x72] ---------------
        u64 sc2[4];
#pragma unroll
        for (int mp = 0; mp < 4; ++mp) sc2[mp] = pack2(scl[2 * mp], scl[2 * mp + 1]);
#pragma unroll
        for (int mp = 0; mp < 4; ++mp)
#pragma unroll
            for (int cp = 0; cp < 5; ++cp)
                o2[mp][cp] = mul2(o2[mp][cp], sc2[mp]);

        const float4* pp = reinterpret_cast<const float4*>(Pt) + tm * 2;
        const float* vp = Vs + bu * BN * 80 + tn * 5;
#pragma unroll 4
        for (int j = 0; j < BN; ++j) {
            F4U2 p0, p1;
            p0.f = pp[j * 33];
            p1.f = pp[j * 33 + 1];
            u64 pr[4] = {p0.u[0], p0.u[1], p1.u[0], p1.u[1]};
            u64 vr[5];
#pragma unroll
            for (int cp = 0; cp < 5; ++cp) {
                float v = vp[j * 80 + cp];
                vr[cp] = pack2(v, v);
            }
#pragma unroll
            for (int mp = 0; mp < 4; ++mp)
#pragma unroll
                for (int cp = 0; cp < 5; ++cp)
                    fma2(o2[mp][cp], pr[mp], vr[cp]);
        }
        __syncthreads();                      // (3) done reading buf & Pt
    }

    // ---------------- epilogue: normalize, then fused grouped pooling -------
    // write wv^T into Qs (Q no longer needed): Qs[c][m] = O[m][c] / l[m]
#pragma unroll
    for (int mp = 0; mp < 4; ++mp) {
        float inv0 = 1.0f / lrow[2 * mp];
        float inv1 = 1.0f / lrow[2 * mp + 1];
        int m = tm * 8 + 2 * mp;
#pragma unroll
        for (int cp = 0; cp < 5; ++cp) {
            int c = tn * 5 + cp;
            if (c < CCH) {
                float v0, v1;
                unpack2(o2[mp][cp], v0, v1);
                Qs[c * BM + m]     = v0 * inv0;
                Qs[c * BM + m + 1] = v1 * inv1;
            }
        }
    }
    __syncthreads();

    // pooled[b][g][n] = sum_{f<4} x[b][4g+f][n] * wv[b][4g+f][n]
    for (int o = tid; o < 18 * BM; o += 256) {
        int m = o & (BM - 1);
        int g = o >> 7;
        float acc = 0.f;
#pragma unroll
        for (int f = 0; f < 4; ++f) {
            int c = 4 * g + f;
            acc = fmaf(x[(size_t)(b * CCH + c) * NPIX + n0 + m], Qs[c * BM + m], acc);
        }
        out[(size_t)(b * 18 + g) * NPIX + n0 + m] = acc;
    }
}

// ---------------------------------------------------------------------------
extern "C" void kernel_launch(void* const* d_in, const int* in_sizes, int n_in,
                              void* d_out, int out_size) {
    const float* x  = (const float*)d_in[0];
    const float* Wq = (const float*)d_in[1];
    const float* bq = (const float*)d_in[2];
    const float* Wk = (const float*)d_in[3];
    const float* bk = (const float*)d_in[4];
    const float* Wv = (const float*)d_in[5];
    const float* bv = (const float*)d_in[6];

    const int smP = (CCH * BM + CCH * CCH + BM * CCH) * 4;               // 94,464 B
    const int smF = (CCH * BM + 2 * CCH * BN + 2 * BN * 80 + BN * 132) * 4; // 148,480 B
    cudaFuncSetAttribute(qkv_kernel,  cudaFuncAttributeMaxDynamicSharedMemorySize, smP);
    cudaFuncSetAttribute(attn_kernel, cudaFuncAttributeMaxDynamicSharedMemorySize, smF);

    qkv_kernel<<<dim3(QTILES, BATCH), 256, smP>>>(x, Wq, bq, Wk, bk, Wv, bv);
    attn_kernel<<<dim3(QTILES, BATCH), 256, smF>>>(x, (float*)d_out);
}